// round 9
// baseline (speedup 1.0000x reference)
#include <cuda_runtime.h>
#include <cuda_bf16.h>
#include <cstdint>
#include <cstddef>

#define H 2048
#define NACT 64
#define STEPS 32
#define NLAYERS 2

// ---------------- device state ----------------
__device__ __align__(16) float g_h[2][NLAYERS][H];   // [parity][layer]
__device__ __align__(16) float g_c[NLAYERS][H];
__device__ __align__(16) float g_x[H];
__device__ __align__(16) float g_part[2][NACT];      // head partial dots
__device__ float g_logp_sum;
__device__ int   g_action;
__device__ int   g_done;

// bf16 weights, HMMA-fragment-ready:
// unit u (16B): lane=u&31, c=(u>>5)&255, T=(u>>13)&511, l=u>>22.
// Tile T covers rows' 16T..16T+15 where row' = j*4+gate (j = 4T + rl/4, gate = rl&3),
// chunk c covers concat-k 16c..16c+15 (k<2048: W_ih, else W_hh).
// 16B = {A[g][k0]A[g][k0+1] | A[g+8][k0..] | A[g][k0+8..] | A[g+8][k0+8..]} bf16 pairs,
// g=lane>>2, k0=16c+2*(lane&3)  == exact m16n8k16 A-fragment for LDG.128 at lane*16.
__device__ __align__(16) unsigned char g_wbf[(size_t)NLAYERS * 2 * 4 * H * H * 2];

// ---------------- threefry2x32-20 (bit-exact JAX core) ----------------
__device__ __forceinline__ uint32_t rotl32(uint32_t v, int d) {
    return (v << d) | (v >> (32 - d));
}
__device__ __forceinline__ void threefry2x32(uint32_t k0, uint32_t k1,
                                             uint32_t x0, uint32_t x1,
                                             uint32_t& o0, uint32_t& o1) {
    const uint32_t ks2 = k0 ^ k1 ^ 0x1BD11BDAu;
    x0 += k0; x1 += k1;
    x0 += x1; x1 = rotl32(x1, 13); x1 ^= x0;
    x0 += x1; x1 = rotl32(x1, 15); x1 ^= x0;
    x0 += x1; x1 = rotl32(x1, 26); x1 ^= x0;
    x0 += x1; x1 = rotl32(x1, 6);  x1 ^= x0;
    x0 += k1; x1 += ks2 + 1u;
    x0 += x1; x1 = rotl32(x1, 17); x1 ^= x0;
    x0 += x1; x1 = rotl32(x1, 29); x1 ^= x0;
    x0 += x1; x1 = rotl32(x1, 16); x1 ^= x0;
    x0 += x1; x1 = rotl32(x1, 24); x1 ^= x0;
    x0 += ks2; x1 += k0 + 2u;
    x0 += x1; x1 = rotl32(x1, 13); x1 ^= x0;
    x0 += x1; x1 = rotl32(x1, 15); x1 ^= x0;
    x0 += x1; x1 = rotl32(x1, 26); x1 ^= x0;
    x0 += x1; x1 = rotl32(x1, 6);  x1 ^= x0;
    x0 += k0; x1 += k1 + 3u;
    x0 += x1; x1 = rotl32(x1, 17); x1 ^= x0;
    x0 += x1; x1 = rotl32(x1, 29); x1 ^= x0;
    x0 += x1; x1 = rotl32(x1, 16); x1 ^= x0;
    x0 += x1; x1 = rotl32(x1, 24); x1 ^= x0;
    x0 += k1; x1 += ks2 + 4u;
    x0 += x1; x1 = rotl32(x1, 13); x1 ^= x0;
    x0 += x1; x1 = rotl32(x1, 15); x1 ^= x0;
    x0 += x1; x1 = rotl32(x1, 26); x1 ^= x0;
    x0 += x1; x1 = rotl32(x1, 6);  x1 ^= x0;
    x0 += ks2; x1 += k0 + 5u;
    o0 = x0; o1 = x1;
}
__device__ __forceinline__ float jax_uniform(uint32_t bits) {
    const float tiny = 1.1754943508222875e-38f;
    uint32_t fb = (bits >> 9) | 0x3f800000u;
    float u = __uint_as_float(fb) - 1.0f;
    u = u * 1.0f + tiny;
    return fmaxf(tiny, u);
}

__device__ __forceinline__ uint32_t bf2_bits(float a, float b) {
    __nv_bfloat162 v = __floats2bfloat162_rn(a, b);
    return *reinterpret_cast<uint32_t*>(&v);
}

// ---------------- weight convert: fp32 -> HMMA-fragment bf16 tiles ----------------
__global__ void convert_kernel(const float* __restrict__ w_ih,
                               const float* __restrict__ w_hh) {
    const size_t NU = (size_t)NLAYERS * 512 * 256 * 32;   // 16B units
    size_t stride = (size_t)gridDim.x * blockDim.x;
    for (size_t u = (size_t)blockIdx.x * blockDim.x + threadIdx.x; u < NU; u += stride) {
        int lane = (int)(u & 31);
        int c    = (int)((u >> 5) & 255);
        int T    = (int)((u >> 13) & 511);
        int l    = (int)(u >> 22);
        int gid  = lane >> 2, t4 = lane & 3;
        int k0c  = 16 * c + 2 * t4;            // concat-k
        int which = k0c >> 11;                  // 0: W_ih, 1: W_hh
        int kk   = k0c & 2047;
        const float* W = (which ? w_hh : w_ih) + (size_t)l * 4 * H * H;
        int rl0 = gid, rl1 = gid + 8;
        int j0 = 4 * T + (rl0 >> 2), g0 = rl0 & 3;
        int j1 = 4 * T + (rl1 >> 2), g1 = rl1 & 3;
        const float* r0p = W + ((size_t)g0 * H + j0) * H;
        const float* r1p = W + ((size_t)g1 * H + j1) * H;
        uint4 o;
        o.x = bf2_bits(r0p[kk],     r0p[kk + 1]);
        o.y = bf2_bits(r1p[kk],     r1p[kk + 1]);
        o.z = bf2_bits(r0p[kk + 8], r0p[kk + 9]);
        o.w = bf2_bits(r1p[kk + 8], r1p[kk + 9]);
        reinterpret_cast<uint4*>(g_wbf)[u] = o;
    }
}

// ---------------- init ----------------
__global__ void init_kernel(const float* __restrict__ start_token) {
    int i = blockIdx.x * blockDim.x + threadIdx.x;
    if (i < H) {
        g_x[i] = start_token[i];
        g_c[0][i] = 0.f; g_c[1][i] = 0.f;
        g_h[0][0][i] = 0.f; g_h[0][1][i] = 0.f;
        g_h[1][0][i] = 0.f; g_h[1][1][i] = 0.f;
        if (i == 0) { g_logp_sum = 0.f; g_action = 0; g_done = 0; }
    }
}

// ---------------- HMMA LSTM cell ----------------
// grid = 256 blocks x 64 threads (2 warps). Warp handles tile T = 2*bid+wid:
// 16 rows' (= 4 j's x 4 gates) over concat K=4096 -> 256 chunk MMAs.
__global__ void __launch_bounds__(64)
cell_kernel(const float* __restrict__ bih, const float* __restrict__ bhh,
            int layer, int t) {
    __shared__ uint32_t sv[2048];        // concat vector as bf16x2 pairs
    __shared__ float sgate[2][16];
    const int tid  = threadIdx.x;
    const int wid  = tid >> 5;
    const int lane = tid & 31;
    const int par_in  = t & 1;
    const int par_out = (t + 1) & 1;

    // build concat vector [x ; h] as bf16 pairs
    {
        const float2* vx = reinterpret_cast<const float2*>(
            (layer == 0) ? g_x : g_h[par_out][0]);
        const float2* vh = reinterpret_cast<const float2*>(g_h[par_in][layer]);
#pragma unroll
        for (int q = tid; q < 2048; q += 64) {
            float2 f = (q < 1024) ? vx[q] : vh[q - 1024];
            sv[q] = bf2_bits(f.x, f.y);
        }
    }
    __syncthreads();

    const int T = blockIdx.x * 2 + wid;
    const uint4* tb = reinterpret_cast<const uint4*>(g_wbf)
                    + ((size_t)(layer * 512 + T) * 256) * 32;
    const int t4 = lane & 3, gid = lane >> 2;

    float c0 = 0.f, c1 = 0.f, c2 = 0.f, c3 = 0.f;
    uint4 a[2][8];
#pragma unroll
    for (int i = 0; i < 8; i++) a[0][i] = tb[i * 32 + lane];

    for (int g = 0; g < 32; g++) {
        const int cur = g & 1;
        if (g < 31) {
            const uint4* nb = tb + (size_t)(g + 1) * 8 * 32;
#pragma unroll
            for (int i = 0; i < 8; i++) a[cur ^ 1][i] = nb[i * 32 + lane];
        }
#pragma unroll
        for (int i = 0; i < 8; i++) {
            const int c = g * 8 + i;
            uint32_t b0 = sv[8 * c + t4];
            uint32_t b1 = sv[8 * c + 4 + t4];
            asm volatile(
                "mma.sync.aligned.m16n8k16.row.col.f32.bf16.bf16.f32 "
                "{%0,%1,%2,%3}, {%4,%5,%6,%7}, {%8,%9}, {%0,%1,%2,%3};"
                : "+f"(c0), "+f"(c1), "+f"(c2), "+f"(c3)
                : "r"(a[cur][i].x), "r"(a[cur][i].y),
                  "r"(a[cur][i].z), "r"(a[cur][i].w),
                  "r"(b0), "r"(b1));
        }
    }

    // C[row'][n]: all n equal (B cols replicated). c0 -> row' gid, c2 -> gid+8.
    sgate[wid][gid]     = c0;
    sgate[wid][gid + 8] = c2;
    __syncwarp();

    if (lane < 4) {
        const int j = 4 * T + lane;
        float gi = sgate[wid][lane * 4 + 0] + bih[j]         + bhh[j];
        float gf = sgate[wid][lane * 4 + 1] + bih[H + j]     + bhh[H + j];
        float gg = sgate[wid][lane * 4 + 2] + bih[2 * H + j] + bhh[2 * H + j];
        float go = sgate[wid][lane * 4 + 3] + bih[3 * H + j] + bhh[3 * H + j];
        float i_ = 1.0f / (1.0f + expf(-gi));
        float f_ = 1.0f / (1.0f + expf(-gf));
        float g_ = tanhf(gg);
        float o_ = 1.0f / (1.0f + expf(-go));
        float cn = f_ * g_c[layer][j] + i_ * g_;
        g_c[layer][j] = cn;
        g_h[par_out][layer][j] = o_ * tanhf(cn);
    }
}

// ---------------- fused head + sample ----------------
__global__ void __launch_bounds__(256)
head_sample_kernel(const float* __restrict__ hw, const float* __restrict__ hb,
                   const float* __restrict__ action_emb,
                   int t, float* __restrict__ out, int out_size) {
    const int r    = blockIdx.x & (NACT - 1);
    const int half = blockIdx.x >> 6;
    const int tid  = threadIdx.x;
    const int par_out = (t + 1) & 1;

    {
        const float4* row = reinterpret_cast<const float4*>(hw + (size_t)r * H);
        const float4* v4  = reinterpret_cast<const float4*>(g_h[par_out][1]);
        int k = half * 256 + tid;
        float4 a = row[k];
        float4 b = v4[k];
        float s = a.x * b.x + a.y * b.y + a.z * b.z + a.w * b.w;
#pragma unroll
        for (int o = 16; o; o >>= 1) s += __shfl_xor_sync(0xffffffffu, s, o);
        __shared__ float sm[8];
        if ((tid & 31) == 0) sm[tid >> 5] = s;
        __syncthreads();
        if (tid == 0) {
            g_part[half][r] = sm[0] + sm[1] + sm[2] + sm[3]
                            + sm[4] + sm[5] + sm[6] + sm[7];
        }
    }

    __shared__ int s_last;
    if (tid == 0) {
        __threadfence();
        int old = atomicAdd(&g_done, 1);
        s_last = (old == 2 * NACT - 1) ? 1 : 0;
        if (s_last) g_done = 0;
    }
    __syncthreads();
    if (!s_last) return;
    __threadfence();

    __shared__ float sl[NACT];
    if (tid < 32) {
        const int lane = tid;
        float l0 = g_part[0][lane]      + g_part[1][lane]      + hb[lane];
        float l1 = g_part[0][lane + 32] + g_part[1][lane + 32] + hb[lane + 32];
        sl[lane] = l0;
        sl[lane + 32] = l1;

        uint32_t kk0, kk1;
        threefry2x32(0u, 42u, 0u, (uint32_t)t, kk0, kk1);
        uint32_t a0, a1, b0, b1;
        threefry2x32(kk0, kk1, 0u, (uint32_t)lane,        a0, a1);
        threefry2x32(kk0, kk1, 0u, (uint32_t)(lane + 32), b0, b1);
        float u0 = jax_uniform(a0 ^ a1);
        float u1 = jax_uniform(b0 ^ b1);
        float gum0 = -logf(-logf(u0));
        float gum1 = -logf(-logf(u1));

        float v0 = l0 + gum0;
        float v1 = l1 + gum1;

        float bestv; int besti;
        if (v1 > v0) { bestv = v1; besti = lane + 32; }
        else         { bestv = v0; besti = lane; }
#pragma unroll
        for (int o = 16; o; o >>= 1) {
            float ov = __shfl_xor_sync(0xffffffffu, bestv, o);
            int   oi = __shfl_xor_sync(0xffffffffu, besti, o);
            if (ov > bestv || (ov == bestv && oi < besti)) { bestv = ov; besti = oi; }
        }
        float mx = fmaxf(l0, l1);
#pragma unroll
        for (int o = 16; o; o >>= 1) mx = fmaxf(mx, __shfl_xor_sync(0xffffffffu, mx, o));
        float se = expf(l0 - mx) + expf(l1 - mx);
#pragma unroll
        for (int o = 16; o; o >>= 1) se += __shfl_xor_sync(0xffffffffu, se, o);

        if (lane == 0) {
            float logp = (sl[besti] - mx) - logf(se);
            float news = g_logp_sum + logp;
            g_logp_sum = news;
            g_action   = besti;
            out[t] = (float)besti;
            if (t == STEPS - 1 && out_size > STEPS) out[STEPS] = news;
        }
    }
    __syncthreads();
    int a = g_action;
    const float* src = action_emb + (size_t)a * H;
    for (int k = tid; k < H; k += 256) g_x[k] = src[k];
}

// ---------------- launch ----------------
extern "C" void kernel_launch(void* const* d_in, const int* in_sizes, int n_in,
                              void* d_out, int out_size) {
    const float* start_token = (const float*)d_in[0];
    const float* action_emb  = (const float*)d_in[1];
    const float* w_ih        = (const float*)d_in[2];
    const float* w_hh        = (const float*)d_in[3];
    const float* b_ih        = (const float*)d_in[4];
    const float* b_hh        = (const float*)d_in[5];
    const float* head_w      = (const float*)d_in[6];
    const float* head_b      = (const float*)d_in[7];
    float* out = (float*)d_out;

    convert_kernel<<<4096, 256>>>(w_ih, w_hh);
    init_kernel<<<(H + 255) / 256, 256>>>(start_token);

    for (int t = 0; t < STEPS; t++) {
        for (int l = 0; l < NLAYERS; l++) {
            cell_kernel<<<256, 64>>>(b_ih + (size_t)l * 4 * H,
                                     b_hh + (size_t)l * 4 * H,
                                     l, t);
        }
        head_sample_kernel<<<2 * NACT, 256>>>(head_w + (size_t)t * NACT * H,
                                              head_b + (size_t)t * NACT,
                                              action_emb, t, out, out_size);
    }
}

// round 11
// speedup vs baseline: 2.9371x; 2.9371x over previous
#include <cuda_runtime.h>
#include <cuda_bf16.h>
#include <cstdint>
#include <cstddef>

#define H 2048
#define NACT 64
#define STEPS 32
#define NLAYERS 2

// ---------------- device state ----------------
__device__ __align__(16) float g_h[2][NLAYERS][H];   // [parity][layer]
__device__ __align__(16) float g_c[NLAYERS][H];
__device__ __align__(16) float g_x[H];
__device__ __align__(16) float g_part[2][NACT];      // head partial dots
__device__ float g_logp_sum;
__device__ int   g_action;
__device__ int   g_done;

// bf16 weights, HMMA-fragment-ready (validated R9):
// unit u (16B): lane=u&31, c=(u>>5)&255, T=(u>>13)&511, l=u>>22.
// Tile T covers rows' 16T..16T+15, row' = j*4+gate; chunk c covers concat-k
// 16c..16c+15 (k<2048: W_ih, else W_hh). The 16B is the exact m16n8k16
// A-fragment for LDG.128 at lane*16.
__device__ __align__(16) unsigned char g_wbf[(size_t)NLAYERS * 2 * 4 * H * H * 2];

// ---------------- threefry2x32-20 (bit-exact JAX core) ----------------
__device__ __forceinline__ uint32_t rotl32(uint32_t v, int d) {
    return (v << d) | (v >> (32 - d));
}
__device__ __forceinline__ void threefry2x32(uint32_t k0, uint32_t k1,
                                             uint32_t x0, uint32_t x1,
                                             uint32_t& o0, uint32_t& o1) {
    const uint32_t ks2 = k0 ^ k1 ^ 0x1BD11BDAu;
    x0 += k0; x1 += k1;
    x0 += x1; x1 = rotl32(x1, 13); x1 ^= x0;
    x0 += x1; x1 = rotl32(x1, 15); x1 ^= x0;
    x0 += x1; x1 = rotl32(x1, 26); x1 ^= x0;
    x0 += x1; x1 = rotl32(x1, 6);  x1 ^= x0;
    x0 += k1; x1 += ks2 + 1u;
    x0 += x1; x1 = rotl32(x1, 17); x1 ^= x0;
    x0 += x1; x1 = rotl32(x1, 29); x1 ^= x0;
    x0 += x1; x1 = rotl32(x1, 16); x1 ^= x0;
    x0 += x1; x1 = rotl32(x1, 24); x1 ^= x0;
    x0 += ks2; x1 += k0 + 2u;
    x0 += x1; x1 = rotl32(x1, 13); x1 ^= x0;
    x0 += x1; x1 = rotl32(x1, 15); x1 ^= x0;
    x0 += x1; x1 = rotl32(x1, 26); x1 ^= x0;
    x0 += x1; x1 = rotl32(x1, 6);  x1 ^= x0;
    x0 += k0; x1 += k1 + 3u;
    x0 += x1; x1 = rotl32(x1, 17); x1 ^= x0;
    x0 += x1; x1 = rotl32(x1, 29); x1 ^= x0;
    x0 += x1; x1 = rotl32(x1, 16); x1 ^= x0;
    x0 += x1; x1 = rotl32(x1, 24); x1 ^= x0;
    x0 += k1; x1 += ks2 + 4u;
    x0 += x1; x1 = rotl32(x1, 13); x1 ^= x0;
    x0 += x1; x1 = rotl32(x1, 15); x1 ^= x0;
    x0 += x1; x1 = rotl32(x1, 26); x1 ^= x0;
    x0 += x1; x1 = rotl32(x1, 6);  x1 ^= x0;
    x0 += ks2; x1 += k0 + 5u;
    o0 = x0; o1 = x1;
}
__device__ __forceinline__ float jax_uniform(uint32_t bits) {
    const float tiny = 1.1754943508222875e-38f;
    uint32_t fb = (bits >> 9) | 0x3f800000u;
    float u = __uint_as_float(fb) - 1.0f;
    u = u * 1.0f + tiny;
    return fmaxf(tiny, u);
}
__device__ __forceinline__ uint32_t bf2_bits(float a, float b) {
    __nv_bfloat162 v = __floats2bfloat162_rn(a, b);
    return *reinterpret_cast<uint32_t*>(&v);
}

// ---------------- weight convert: fp32 -> HMMA-fragment bf16 tiles ----------------
__global__ void convert_kernel(const float* __restrict__ w_ih,
                               const float* __restrict__ w_hh) {
    const size_t NU = (size_t)NLAYERS * 512 * 256 * 32;   // 16B units
    size_t stride = (size_t)gridDim.x * blockDim.x;
    for (size_t u = (size_t)blockIdx.x * blockDim.x + threadIdx.x; u < NU; u += stride) {
        int lane = (int)(u & 31);
        int c    = (int)((u >> 5) & 255);
        int T    = (int)((u >> 13) & 511);
        int l    = (int)(u >> 22);
        int gid  = lane >> 2, t4 = lane & 3;
        int k0c  = 16 * c + 2 * t4;            // concat-k
        int which = k0c >> 11;                  // 0: W_ih, 1: W_hh
        int kk   = k0c & 2047;
        const float* W = (which ? w_hh : w_ih) + (size_t)l * 4 * H * H;
        int rl0 = gid, rl1 = gid + 8;
        int j0 = 4 * T + (rl0 >> 2), g0 = rl0 & 3;
        int j1 = 4 * T + (rl1 >> 2), g1 = rl1 & 3;
        const float* r0p = W + ((size_t)g0 * H + j0) * H;
        const float* r1p = W + ((size_t)g1 * H + j1) * H;
        uint4 o;
        o.x = bf2_bits(r0p[kk],     r0p[kk + 1]);
        o.y = bf2_bits(r1p[kk],     r1p[kk + 1]);
        o.z = bf2_bits(r0p[kk + 8], r0p[kk + 9]);
        o.w = bf2_bits(r1p[kk + 8], r1p[kk + 9]);
        reinterpret_cast<uint4*>(g_wbf)[u] = o;
    }
}

// ---------------- init ----------------
__global__ void init_kernel(const float* __restrict__ start_token) {
    int i = blockIdx.x * blockDim.x + threadIdx.x;
    if (i < H) {
        g_x[i] = start_token[i];
        g_c[0][i] = 0.f; g_c[1][i] = 0.f;
        g_h[0][0][i] = 0.f; g_h[0][1][i] = 0.f;
        g_h[1][0][i] = 0.f; g_h[1][1][i] = 0.f;
        if (i == 0) { g_logp_sum = 0.f; g_action = 0; g_done = 0; }
    }
}

// ---------------- HMMA LSTM cell, K-split 8 ----------------
// grid = 512 blocks x 256 threads (8 warps). Block = tile T (16 rows' = 4 j x
// 4 gates over concat K=4096). Warp w handles chunks [32w, 32w+32) (K=512),
// depth-4 double-buffered. Partials reduced via smem; warp 0 fuses gates.
__global__ void __launch_bounds__(256)
cell_kernel(const float* __restrict__ bih, const float* __restrict__ bhh,
            int layer, int t) {
    __shared__ uint32_t sv[2048];        // concat [x;h] as bf16x2 pairs
    __shared__ float spart[8][16];
    const int tid  = threadIdx.x;
    const int wid  = tid >> 5;
    const int lane = tid & 31;
    const int par_in  = t & 1;
    const int par_out = (t + 1) & 1;

    // build concat vector
    {
        const float2* vx = reinterpret_cast<const float2*>(
            (layer == 0) ? g_x : g_h[par_out][0]);
        const float2* vh = reinterpret_cast<const float2*>(g_h[par_in][layer]);
#pragma unroll
        for (int q = tid; q < 2048; q += 256) {
            float2 f = (q < 1024) ? vx[q] : vh[q - 1024];
            sv[q] = bf2_bits(f.x, f.y);
        }
    }
    __syncthreads();

    const int T = blockIdx.x;
    const uint4* wb = reinterpret_cast<const uint4*>(g_wbf)
                    + ((size_t)(layer * 512 + T) * 256 + 32 * wid) * 32;
    const int t4 = lane & 3, gid = lane >> 2;

    float c0 = 0.f, c1 = 0.f, c2 = 0.f, c3 = 0.f;
    uint4 a[2][4];
#pragma unroll
    for (int i = 0; i < 4; i++) a[0][i] = wb[i * 32 + lane];

    for (int g = 0; g < 8; g++) {
        const int cur = g & 1;
        if (g < 7) {
            const uint4* nb = wb + (size_t)(g + 1) * 4 * 32;
#pragma unroll
            for (int i = 0; i < 4; i++) a[cur ^ 1][i] = nb[i * 32 + lane];
        }
#pragma unroll
        for (int i = 0; i < 4; i++) {
            const int c = 32 * wid + g * 4 + i;
            uint32_t b0 = sv[8 * c + t4];
            uint32_t b1 = sv[8 * c + 4 + t4];
            asm volatile(
                "mma.sync.aligned.m16n8k16.row.col.f32.bf16.bf16.f32 "
                "{%0,%1,%2,%3}, {%4,%5,%6,%7}, {%8,%9}, {%0,%1,%2,%3};"
                : "+f"(c0), "+f"(c1), "+f"(c2), "+f"(c3)
                : "r"(a[cur][i].x), "r"(a[cur][i].y),
                  "r"(a[cur][i].z), "r"(a[cur][i].w),
                  "r"(b0), "r"(b1));
        }
    }

    // C columns all equal: c0 = row' gid partial, c2 = row' gid+8 partial.
    if (t4 == 0) {
        spart[wid][gid]     = c0;
        spart[wid][gid + 8] = c2;
    }
    __syncthreads();

    if (tid < 4) {
        const int j = 4 * T + tid;
        float gate[4];
#pragma unroll
        for (int gt = 0; gt < 4; gt++) {
            const int rl = tid * 4 + gt;
            float s = 0.f;
#pragma unroll
            for (int k = 0; k < 8; k++) s += spart[k][rl];
            gate[gt] = s;
        }
        float gi = gate[0] + bih[j]         + bhh[j];
        float gf = gate[1] + bih[H + j]     + bhh[H + j];
        float gg = gate[2] + bih[2 * H + j] + bhh[2 * H + j];
        float go = gate[3] + bih[3 * H + j] + bhh[3 * H + j];
        float i_ = 1.0f / (1.0f + expf(-gi));
        float f_ = 1.0f / (1.0f + expf(-gf));
        float g_ = tanhf(gg);
        float o_ = 1.0f / (1.0f + expf(-go));
        float cn = f_ * g_c[layer][j] + i_ * g_;
        g_c[layer][j] = cn;
        g_h[par_out][layer][j] = o_ * tanhf(cn);
    }
}

// ---------------- fused head + sample ----------------
__global__ void __launch_bounds__(256)
head_sample_kernel(const float* __restrict__ hw, const float* __restrict__ hb,
                   const float* __restrict__ action_emb,
                   int t, float* __restrict__ out, int out_size) {
    const int r    = blockIdx.x & (NACT - 1);
    const int half = blockIdx.x >> 6;
    const int tid  = threadIdx.x;
    const int par_out = (t + 1) & 1;

    {
        const float4* row = reinterpret_cast<const float4*>(hw + (size_t)r * H);
        const float4* v4  = reinterpret_cast<const float4*>(g_h[par_out][1]);
        int k = half * 256 + tid;
        float4 a = row[k];
        float4 b = v4[k];
        float s = a.x * b.x + a.y * b.y + a.z * b.z + a.w * b.w;
#pragma unroll
        for (int o = 16; o; o >>= 1) s += __shfl_xor_sync(0xffffffffu, s, o);
        __shared__ float sm[8];
        if ((tid & 31) == 0) sm[tid >> 5] = s;
        __syncthreads();
        if (tid == 0) {
            g_part[half][r] = sm[0] + sm[1] + sm[2] + sm[3]
                            + sm[4] + sm[5] + sm[6] + sm[7];
        }
    }

    __shared__ int s_last;
    if (tid == 0) {
        __threadfence();
        int old = atomicAdd(&g_done, 1);
        s_last = (old == 2 * NACT - 1) ? 1 : 0;
        if (s_last) g_done = 0;
    }
    __syncthreads();
    if (!s_last) return;
    __threadfence();

    __shared__ float sl[NACT];
    if (tid < 32) {
        const int lane = tid;
        float l0 = g_part[0][lane]      + g_part[1][lane]      + hb[lane];
        float l1 = g_part[0][lane + 32] + g_part[1][lane + 32] + hb[lane + 32];
        sl[lane] = l0;
        sl[lane + 32] = l1;

        uint32_t kk0, kk1;
        threefry2x32(0u, 42u, 0u, (uint32_t)t, kk0, kk1);
        uint32_t a0, a1, b0, b1;
        threefry2x32(kk0, kk1, 0u, (uint32_t)lane,        a0, a1);
        threefry2x32(kk0, kk1, 0u, (uint32_t)(lane + 32), b0, b1);
        float u0 = jax_uniform(a0 ^ a1);
        float u1 = jax_uniform(b0 ^ b1);
        float gum0 = -logf(-logf(u0));
        float gum1 = -logf(-logf(u1));

        float v0 = l0 + gum0;
        float v1 = l1 + gum1;

        float bestv; int besti;
        if (v1 > v0) { bestv = v1; besti = lane + 32; }
        else         { bestv = v0; besti = lane; }
#pragma unroll
        for (int o = 16; o; o >>= 1) {
            float ov = __shfl_xor_sync(0xffffffffu, bestv, o);
            int   oi = __shfl_xor_sync(0xffffffffu, besti, o);
            if (ov > bestv || (ov == bestv && oi < besti)) { bestv = ov; besti = oi; }
        }
        float mx = fmaxf(l0, l1);
#pragma unroll
        for (int o = 16; o; o >>= 1) mx = fmaxf(mx, __shfl_xor_sync(0xffffffffu, mx, o));
        float se = expf(l0 - mx) + expf(l1 - mx);
#pragma unroll
        for (int o = 16; o; o >>= 1) se += __shfl_xor_sync(0xffffffffu, se, o);

        if (lane == 0) {
            float logp = (sl[besti] - mx) - logf(se);
            float news = g_logp_sum + logp;
            g_logp_sum = news;
            g_action   = besti;
            out[t] = (float)besti;
            if (t == STEPS - 1 && out_size > STEPS) out[STEPS] = news;
        }
    }
    __syncthreads();
    int a = g_action;
    const float* src = action_emb + (size_t)a * H;
    for (int k = tid; k < H; k += 256) g_x[k] = src[k];
}

// ---------------- launch ----------------
extern "C" void kernel_launch(void* const* d_in, const int* in_sizes, int n_in,
                              void* d_out, int out_size) {
    const float* start_token = (const float*)d_in[0];
    const float* action_emb  = (const float*)d_in[1];
    const float* w_ih        = (const float*)d_in[2];
    const float* w_hh        = (const float*)d_in[3];
    const float* b_ih        = (const float*)d_in[4];
    const float* b_hh        = (const float*)d_in[5];
    const float* head_w      = (const float*)d_in[6];
    const float* head_b      = (const float*)d_in[7];
    float* out = (float*)d_out;

    convert_kernel<<<4096, 256>>>(w_ih, w_hh);
    init_kernel<<<(H + 255) / 256, 256>>>(start_token);

    for (int t = 0; t < STEPS; t++) {
        for (int l = 0; l < NLAYERS; l++) {
            cell_kernel<<<512, 256>>>(b_ih + (size_t)l * 4 * H,
                                      b_hh + (size_t)l * 4 * H,
                                      l, t);
        }
        head_sample_kernel<<<2 * NACT, 256>>>(head_w + (size_t)t * NACT * H,
                                              head_b + (size_t)t * NACT,
                                              action_emb, t, out, out_size);
    }
}

// round 12
// speedup vs baseline: 2.9956x; 1.0199x over previous
#include <cuda_runtime.h>
#include <cuda_bf16.h>
#include <cstdint>
#include <cstddef>

#define H 2048
#define NACT 64
#define STEPS 32
#define NLAYERS 2

// ---------------- device state ----------------
__device__ __align__(16) float g_h[2][NLAYERS][H];   // [parity][layer]
__device__ __align__(16) float g_c[NLAYERS][H];
__device__ __align__(16) float g_x[H];
__device__ __align__(16) float g_part[2][NACT];      // head partial dots
__device__ float g_logp_sum;
__device__ int   g_action;
__device__ int   g_done;

// bf16 weights, HMMA-fragment-ready (validated R9/R11):
// unit u (16B): lane=u&31, c=(u>>5)&255, T=(u>>13)&511, l=u>>22.
// Tile T covers rows' 16T..16T+15, row' = j*4+gate; chunk c covers concat-k
// 16c..16c+15 (k<2048: W_ih, else W_hh). The 16B is the exact m16n8k16
// A-fragment for LDG.128 at lane*16.
__device__ __align__(16) unsigned char g_wbf[(size_t)NLAYERS * 2 * 4 * H * H * 2];

// ---------------- threefry2x32-20 (bit-exact JAX core) ----------------
__device__ __forceinline__ uint32_t rotl32(uint32_t v, int d) {
    return (v << d) | (v >> (32 - d));
}
__device__ __forceinline__ void threefry2x32(uint32_t k0, uint32_t k1,
                                             uint32_t x0, uint32_t x1,
                                             uint32_t& o0, uint32_t& o1) {
    const uint32_t ks2 = k0 ^ k1 ^ 0x1BD11BDAu;
    x0 += k0; x1 += k1;
    x0 += x1; x1 = rotl32(x1, 13); x1 ^= x0;
    x0 += x1; x1 = rotl32(x1, 15); x1 ^= x0;
    x0 += x1; x1 = rotl32(x1, 26); x1 ^= x0;
    x0 += x1; x1 = rotl32(x1, 6);  x1 ^= x0;
    x0 += k1; x1 += ks2 + 1u;
    x0 += x1; x1 = rotl32(x1, 17); x1 ^= x0;
    x0 += x1; x1 = rotl32(x1, 29); x1 ^= x0;
    x0 += x1; x1 = rotl32(x1, 16); x1 ^= x0;
    x0 += x1; x1 = rotl32(x1, 24); x1 ^= x0;
    x0 += ks2; x1 += k0 + 2u;
    x0 += x1; x1 = rotl32(x1, 13); x1 ^= x0;
    x0 += x1; x1 = rotl32(x1, 15); x1 ^= x0;
    x0 += x1; x1 = rotl32(x1, 26); x1 ^= x0;
    x0 += x1; x1 = rotl32(x1, 6);  x1 ^= x0;
    x0 += k0; x1 += k1 + 3u;
    x0 += x1; x1 = rotl32(x1, 17); x1 ^= x0;
    x0 += x1; x1 = rotl32(x1, 29); x1 ^= x0;
    x0 += x1; x1 = rotl32(x1, 16); x1 ^= x0;
    x0 += x1; x1 = rotl32(x1, 24); x1 ^= x0;
    x0 += k1; x1 += ks2 + 4u;
    x0 += x1; x1 = rotl32(x1, 13); x1 ^= x0;
    x0 += x1; x1 = rotl32(x1, 15); x1 ^= x0;
    x0 += x1; x1 = rotl32(x1, 26); x1 ^= x0;
    x0 += x1; x1 = rotl32(x1, 6);  x1 ^= x0;
    x0 += ks2; x1 += k0 + 5u;
    o0 = x0; o1 = x1;
}
__device__ __forceinline__ float jax_uniform(uint32_t bits) {
    const float tiny = 1.1754943508222875e-38f;
    uint32_t fb = (bits >> 9) | 0x3f800000u;
    float u = __uint_as_float(fb) - 1.0f;
    u = u * 1.0f + tiny;
    return fmaxf(tiny, u);
}
__device__ __forceinline__ uint32_t bf2_bits(float a, float b) {
    __nv_bfloat162 v = __floats2bfloat162_rn(a, b);
    return *reinterpret_cast<uint32_t*>(&v);
}

// ---------------- weight convert: fp32 -> HMMA-fragment bf16 tiles ----------------
__global__ void convert_kernel(const float* __restrict__ w_ih,
                               const float* __restrict__ w_hh) {
    const size_t NU = (size_t)NLAYERS * 512 * 256 * 32;   // 16B units
    size_t stride = (size_t)gridDim.x * blockDim.x;
    for (size_t u = (size_t)blockIdx.x * blockDim.x + threadIdx.x; u < NU; u += stride) {
        int lane = (int)(u & 31);
        int c    = (int)((u >> 5) & 255);
        int T    = (int)((u >> 13) & 511);
        int l    = (int)(u >> 22);
        int gid  = lane >> 2, t4 = lane & 3;
        int k0c  = 16 * c + 2 * t4;            // concat-k
        int which = k0c >> 11;                  // 0: W_ih, 1: W_hh
        int kk   = k0c & 2047;
        const float* W = (which ? w_hh : w_ih) + (size_t)l * 4 * H * H;
        int rl0 = gid, rl1 = gid + 8;
        int j0 = 4 * T + (rl0 >> 2), g0 = rl0 & 3;
        int j1 = 4 * T + (rl1 >> 2), g1 = rl1 & 3;
        const float* r0p = W + ((size_t)g0 * H + j0) * H;
        const float* r1p = W + ((size_t)g1 * H + j1) * H;
        uint4 o;
        o.x = bf2_bits(r0p[kk],     r0p[kk + 1]);
        o.y = bf2_bits(r1p[kk],     r1p[kk + 1]);
        o.z = bf2_bits(r0p[kk + 8], r0p[kk + 9]);
        o.w = bf2_bits(r1p[kk + 8], r1p[kk + 9]);
        reinterpret_cast<uint4*>(g_wbf)[u] = o;
    }
}

// ---------------- init ----------------
__global__ void init_kernel(const float* __restrict__ start_token) {
    int i = blockIdx.x * blockDim.x + threadIdx.x;
    if (i < H) {
        g_x[i] = start_token[i];
        g_c[0][i] = 0.f; g_c[1][i] = 0.f;
        g_h[0][0][i] = 0.f; g_h[0][1][i] = 0.f;
        g_h[1][0][i] = 0.f; g_h[1][1][i] = 0.f;
        if (i == 0) { g_logp_sum = 0.f; g_action = 0; g_done = 0; }
    }
}

// ---------------- HMMA LSTM cell, K-split 16 ----------------
// grid = 512 blocks x 512 threads (16 warps). Block = tile T (16 rows' = 4 j x
// 4 gates over concat K=4096). Warp w handles chunks [16w, 16w+16) (K=256,
// 8 KB stream), groups of 4 double-buffered. Partials via smem; 4 threads fuse.
__global__ void __launch_bounds__(512)
cell_kernel(const float* __restrict__ bih, const float* __restrict__ bhh,
            int layer, int t) {
    __shared__ uint32_t sv[2048];        // concat [x;h] as bf16x2 pairs
    __shared__ float spart[16][16];
    const int tid  = threadIdx.x;
    const int wid  = tid >> 5;
    const int lane = tid & 31;
    const int par_in  = t & 1;
    const int par_out = (t + 1) & 1;

    // build concat vector
    {
        const float2* vx = reinterpret_cast<const float2*>(
            (layer == 0) ? g_x : g_h[par_out][0]);
        const float2* vh = reinterpret_cast<const float2*>(g_h[par_in][layer]);
#pragma unroll
        for (int q = tid; q < 2048; q += 512) {
            float2 f = (q < 1024) ? vx[q] : vh[q - 1024];
            sv[q] = bf2_bits(f.x, f.y);
        }
    }
    __syncthreads();

    const int T = blockIdx.x;
    const uint4* wb = reinterpret_cast<const uint4*>(g_wbf)
                    + ((size_t)(layer * 512 + T) * 256 + 16 * wid) * 32;
    const int t4 = lane & 3, gid = lane >> 2;

    float c0 = 0.f, c1 = 0.f, c2 = 0.f, c3 = 0.f;
    uint4 a[2][4];
#pragma unroll
    for (int i = 0; i < 4; i++) a[0][i] = wb[i * 32 + lane];

#pragma unroll
    for (int g = 0; g < 4; g++) {
        const int cur = g & 1;
        if (g < 3) {
            const uint4* nb = wb + (size_t)(g + 1) * 4 * 32;
#pragma unroll
            for (int i = 0; i < 4; i++) a[cur ^ 1][i] = nb[i * 32 + lane];
        }
#pragma unroll
        for (int i = 0; i < 4; i++) {
            const int c = 16 * wid + g * 4 + i;
            uint32_t b0 = sv[8 * c + t4];
            uint32_t b1 = sv[8 * c + 4 + t4];
            asm volatile(
                "mma.sync.aligned.m16n8k16.row.col.f32.bf16.bf16.f32 "
                "{%0,%1,%2,%3}, {%4,%5,%6,%7}, {%8,%9}, {%0,%1,%2,%3};"
                : "+f"(c0), "+f"(c1), "+f"(c2), "+f"(c3)
                : "r"(a[cur][i].x), "r"(a[cur][i].y),
                  "r"(a[cur][i].z), "r"(a[cur][i].w),
                  "r"(b0), "r"(b1));
        }
    }

    // C columns all equal: c0 = row' gid partial, c2 = row' gid+8 partial.
    if (t4 == 0) {
        spart[wid][gid]     = c0;
        spart[wid][gid + 8] = c2;
    }
    __syncthreads();

    if (tid < 4) {
        const int j = 4 * T + tid;
        float gate[4];
#pragma unroll
        for (int gt = 0; gt < 4; gt++) {
            const int rl = tid * 4 + gt;
            float s = 0.f;
#pragma unroll
            for (int k = 0; k < 16; k++) s += spart[k][rl];
            gate[gt] = s;
        }
        float gi = gate[0] + bih[j]         + bhh[j];
        float gf = gate[1] + bih[H + j]     + bhh[H + j];
        float gg = gate[2] + bih[2 * H + j] + bhh[2 * H + j];
        float go = gate[3] + bih[3 * H + j] + bhh[3 * H + j];
        float i_ = 1.0f / (1.0f + expf(-gi));
        float f_ = 1.0f / (1.0f + expf(-gf));
        float g_ = tanhf(gg);
        float o_ = 1.0f / (1.0f + expf(-go));
        float cn = f_ * g_c[layer][j] + i_ * g_;
        g_c[layer][j] = cn;
        g_h[par_out][layer][j] = o_ * tanhf(cn);
    }
}

// ---------------- fused head + sample ----------------
__global__ void __launch_bounds__(256)
head_sample_kernel(const float* __restrict__ hw, const float* __restrict__ hb,
                   const float* __restrict__ action_emb,
                   int t, float* __restrict__ out, int out_size) {
    const int r    = blockIdx.x & (NACT - 1);
    const int half = blockIdx.x >> 6;
    const int tid  = threadIdx.x;
    const int par_out = (t + 1) & 1;

    {
        const float4* row = reinterpret_cast<const float4*>(hw + (size_t)r * H);
        const float4* v4  = reinterpret_cast<const float4*>(g_h[par_out][1]);
        int k = half * 256 + tid;
        float4 a = row[k];
        float4 b = v4[k];
        float s = a.x * b.x + a.y * b.y + a.z * b.z + a.w * b.w;
#pragma unroll
        for (int o = 16; o; o >>= 1) s += __shfl_xor_sync(0xffffffffu, s, o);
        __shared__ float sm[8];
        if ((tid & 31) == 0) sm[tid >> 5] = s;
        __syncthreads();
        if (tid == 0) {
            g_part[half][r] = sm[0] + sm[1] + sm[2] + sm[3]
                            + sm[4] + sm[5] + sm[6] + sm[7];
        }
    }

    __shared__ int s_last;
    if (tid == 0) {
        __threadfence();
        int old = atomicAdd(&g_done, 1);
        s_last = (old == 2 * NACT - 1) ? 1 : 0;
        if (s_last) g_done = 0;
    }
    __syncthreads();
    if (!s_last) return;
    __threadfence();

    __shared__ float sl[NACT];
    if (tid < 32) {
        const int lane = tid;
        float l0 = g_part[0][lane]      + g_part[1][lane]      + hb[lane];
        float l1 = g_part[0][lane + 32] + g_part[1][lane + 32] + hb[lane + 32];
        sl[lane] = l0;
        sl[lane + 32] = l1;

        uint32_t kk0, kk1;
        threefry2x32(0u, 42u, 0u, (uint32_t)t, kk0, kk1);
        uint32_t a0, a1, b0, b1;
        threefry2x32(kk0, kk1, 0u, (uint32_t)lane,        a0, a1);
        threefry2x32(kk0, kk1, 0u, (uint32_t)(lane + 32), b0, b1);
        float u0 = jax_uniform(a0 ^ a1);
        float u1 = jax_uniform(b0 ^ b1);
        float gum0 = -logf(-logf(u0));
        float gum1 = -logf(-logf(u1));

        float v0 = l0 + gum0;
        float v1 = l1 + gum1;

        float bestv; int besti;
        if (v1 > v0) { bestv = v1; besti = lane + 32; }
        else         { bestv = v0; besti = lane; }
#pragma unroll
        for (int o = 16; o; o >>= 1) {
            float ov = __shfl_xor_sync(0xffffffffu, bestv, o);
            int   oi = __shfl_xor_sync(0xffffffffu, besti, o);
            if (ov > bestv || (ov == bestv && oi < besti)) { bestv = ov; besti = oi; }
        }
        float mx = fmaxf(l0, l1);
#pragma unroll
        for (int o = 16; o; o >>= 1) mx = fmaxf(mx, __shfl_xor_sync(0xffffffffu, mx, o));
        float se = expf(l0 - mx) + expf(l1 - mx);
#pragma unroll
        for (int o = 16; o; o >>= 1) se += __shfl_xor_sync(0xffffffffu, se, o);

        if (lane == 0) {
            float logp = (sl[besti] - mx) - logf(se);
            float news = g_logp_sum + logp;
            g_logp_sum = news;
            g_action   = besti;
            out[t] = (float)besti;
            if (t == STEPS - 1 && out_size > STEPS) out[STEPS] = news;
        }
    }
    __syncthreads();
    int a = g_action;
    const float* src = action_emb + (size_t)a * H;
    for (int k = tid; k < H; k += 256) g_x[k] = src[k];
}

// ---------------- launch ----------------
extern "C" void kernel_launch(void* const* d_in, const int* in_sizes, int n_in,
                              void* d_out, int out_size) {
    const float* start_token = (const float*)d_in[0];
    const float* action_emb  = (const float*)d_in[1];
    const float* w_ih        = (const float*)d_in[2];
    const float* w_hh        = (const float*)d_in[3];
    const float* b_ih        = (const float*)d_in[4];
    const float* b_hh        = (const float*)d_in[5];
    const float* head_w      = (const float*)d_in[6];
    const float* head_b      = (const float*)d_in[7];
    float* out = (float*)d_out;

    convert_kernel<<<4096, 256>>>(w_ih, w_hh);
    init_kernel<<<(H + 255) / 256, 256>>>(start_token);

    for (int t = 0; t < STEPS; t++) {
        for (int l = 0; l < NLAYERS; l++) {
            cell_kernel<<<512, 512>>>(b_ih + (size_t)l * 4 * H,
                                      b_hh + (size_t)l * 4 * H,
                                      l, t);
        }
        head_sample_kernel<<<2 * NACT, 256>>>(head_w + (size_t)t * NACT * H,
                                              head_b + (size_t)t * NACT,
                                              action_emb, t, out, out_size);
    }
}